// round 8
// baseline (speedup 1.0000x reference)
#include <cuda_runtime.h>

#define BB      512
#define INF     512
#define OUTF    64
#define KK      16
#define NN      1024   // OUTF * KK
#define OUTCOLS 576    // INF + OUTF
#define THRESH  120.0f

typedef unsigned long long ull;

// Scratch (static device allocs are allowed).
__device__ float g_M[BB * NN];              // 2MB: M = x @ T
__device__ float g_G[OUTF * BB * 8];        // 1MB: 8 group-sums per (o,i)
__device__ ull   g_mask[OUTF * 8 * BB];     // 2MB: survivor bitmasks (j>i only)

#define FMA2D(d, a, b, c) \
    asm("fma.rn.f32x2 %0, %1, %2, %3;" : "=l"(d) : "l"(a), "l"(b), "l"(c))
#define ADD2(d, a, b) \
    asm("add.rn.f32x2 %0, %1, %2;" : "=l"(d) : "l"(a), "l"(b))

__device__ __forceinline__ void mma_tf32(float* c, const unsigned* a, const unsigned* b) {
    asm("mma.sync.aligned.m16n8k8.row.col.f32.tf32.tf32.f32 "
        "{%0,%1,%2,%3}, {%4,%5,%6,%7}, {%8,%9}, {%0,%1,%2,%3};"
        : "+f"(c[0]), "+f"(c[1]), "+f"(c[2]), "+f"(c[3])
        : "r"(a[0]), "r"(a[1]), "r"(a[2]), "r"(a[3]), "r"(b[0]), "r"(b[1]));
}

// ---------------------------------------------------------------------------
// GEMM via tf32 tensor cores, double-buffered: M = x(512x512) @ T(512x1024).
// Block 256 thr (8 warps, warp = n8 slice), tile 16x64, k-tile 32.
// Grid (16,32) = 512 blocks. Epilogue writes g_M + group sums g_G and
// zero-inits out[:,512:576].
// ---------------------------------------------------------------------------
__global__ __launch_bounds__(256) void gemm_tc(const float* __restrict__ x,
                                               const float* __restrict__ T,
                                               float* __restrict__ out) {
    __shared__ float As[2][16][36];
    __shared__ float Bs[2][32][68];

    const int tid  = threadIdx.x;
    const int warp = tid >> 5;     // 0..7, owns cols [warp*8, warp*8+8)
    const int lane = tid & 31;
    const int tg   = lane >> 2;    // 0..7
    const int tig  = lane & 3;     // 0..3

    const int rowBase = blockIdx.y * 16;
    const int colBase = blockIdx.x * 64;

    // Zero-init the o_b region of out (32768 elements over 512 blocks).
    {
        int idx = (blockIdx.y * 16 + blockIdx.x) * 64 + (tid & 63);
        if (tid < 64) out[(idx >> 6) * OUTCOLS + INF + (idx & 63)] = 0.f;
    }

    const int ar  = tid >> 3;            // A row (0..15) for tid<128
    const int akq = (tid & 7) * 4;       // A k-quad
    const int bk  = tid >> 4;            // B k row (0..15, +16)
    const int bnq = (tid & 15) * 4;      // B n-quad

    // Prologue: tile 0 -> buffer 0.
    if (tid < 128)
        *(float4*)&As[0][ar][akq] = *(const float4*)&x[(rowBase + ar) * INF + akq];
    *(float4*)&Bs[0][bk][bnq]      = *(const float4*)&T[bk * NN + colBase + bnq];
    *(float4*)&Bs[0][bk + 16][bnq] = *(const float4*)&T[(bk + 16) * NN + colBase + bnq];
    __syncthreads();

    float acc[4] = {0.f, 0.f, 0.f, 0.f};
    float4 pa, pb0, pb1;

    for (int it = 0; it < 16; ++it) {
        const int cur = it & 1;
        const int nxt = cur ^ 1;
        const int k0n = (it + 1) * 32;

        if (it < 15) {
            if (tid < 128)
                pa = *(const float4*)&x[(rowBase + ar) * INF + k0n + akq];
            pb0 = *(const float4*)&T[(k0n + bk) * NN + colBase + bnq];
            pb1 = *(const float4*)&T[(k0n + bk + 16) * NN + colBase + bnq];
        }

#pragma unroll
        for (int ks = 0; ks < 32; ks += 8) {
            unsigned a[4], b[2];
            a[0] = __float_as_uint(As[cur][tg][ks + tig]);
            a[1] = __float_as_uint(As[cur][tg + 8][ks + tig]);
            a[2] = __float_as_uint(As[cur][tg][ks + tig + 4]);
            a[3] = __float_as_uint(As[cur][tg + 8][ks + tig + 4]);
            int colB = warp * 8 + tg;
            b[0] = __float_as_uint(Bs[cur][ks + tig][colB]);
            b[1] = __float_as_uint(Bs[cur][ks + tig + 4][colB]);
            mma_tf32(acc, a, b);
        }

        if (it < 15) {
            if (tid < 128)
                *(float4*)&As[nxt][ar][akq] = pa;
            *(float4*)&Bs[nxt][bk][bnq]      = pb0;
            *(float4*)&Bs[nxt][bk + 16][bnq] = pb1;
            __syncthreads();
        }
    }

    // Epilogue: g_M + adjacent-pair group sums g_G.
    {
        int row0 = rowBase + tg;
        int col0 = colBase + warp * 8 + tig * 2;
        int o = col0 >> 4;
        int g = (col0 & 15) >> 1;
        *(float2*)&g_M[row0 * NN + col0]       = make_float2(acc[0], acc[1]);
        *(float2*)&g_M[(row0 + 8) * NN + col0] = make_float2(acc[2], acc[3]);
        g_G[((o << 9) + row0) * 8 + g]     = acc[0] + acc[1];
        g_G[((o << 9) + row0 + 8) * 8 + g] = acc[2] + acc[3];
    }
}

// ---------------------------------------------------------------------------
// Stage 1: symmetric lower-bound filter -> bitmask (bits only for j > i).
// Grid (65, 8), 512 threads. o == 64: copy x rows into out[:, 0:512].
// ---------------------------------------------------------------------------
__global__ __launch_bounds__(512) void stage1_mask(const float* __restrict__ x,
                                                   float* __restrict__ out) {
    __shared__ __align__(16) ull sG[64 * 4];   // 64 j-rows x 4 packed group-pairs

    const int o   = blockIdx.x;
    const int ec  = blockIdx.y;
    const int tid = threadIdx.x;

    if (o == OUTF) {
        int base = ec * 64;
#pragma unroll
        for (int t = tid; t < 64 * (INF / 4); t += 512) {
            int r = t >> 7;
            int c = t & 127;
            float4 v = *(const float4*)&x[(base + r) * INF + c * 4];
            *(float4*)&out[(base + r) * OUTCOLS + c * 4] = v;
        }
        return;
    }

    const int jbase = ec * 64;
    const int i     = tid;
    const int lim   = i - jbase;   // bits jj <= lim cleared (keep j > i)

    if (tid < 128) {
        int r = tid >> 1;
        int h = tid & 1;
        *(float4*)&sG[r * 4 + h * 2] =
            *(const float4*)&g_G[((o << 9) + jbase + r) * 8 + h * 4];
    }

    ull gi[4];
    {
        const ulonglong2* p = (const ulonglong2*)&g_G[((o << 9) + i) * 8];
        ulonglong2 v0 = p[0], v1 = p[1];
        gi[0] = v0.x; gi[1] = v0.y; gi[2] = v1.x; gi[3] = v1.y;
    }
    __syncthreads();

    const ull NEG1  = 0xBF800000BF800000ULL;
    const ull AMASK = 0x7FFFFFFF7FFFFFFFULL;

    ull msk = 0;
    if (lim < 63) {
#pragma unroll
        for (int jj = 0; jj < 64; ++jj) {
            const ulonglong2* p = (const ulonglong2*)&sG[jj * 4];
            ulonglong2 v0 = p[0], v1 = p[1];

            ull d0, d1, d2, d3;
            FMA2D(d0, v0.x, NEG1, gi[0]);
            FMA2D(d1, v0.y, NEG1, gi[1]);
            FMA2D(d2, v1.x, NEG1, gi[2]);
            FMA2D(d3, v1.y, NEG1, gi[3]);
            d0 &= AMASK; d1 &= AMASK; d2 &= AMASK; d3 &= AMASK;

            ull s0, s1, t;
            ADD2(s0, d0, d1);
            ADD2(s1, d2, d3);
            ADD2(t, s0, s1);

            float lb = __uint_as_float((unsigned)t) + __uint_as_float((unsigned)(t >> 32));
            if (lb < THRESH) msk |= (1ULL << jj);
        }
        if (lim >= 0) msk &= ~((2ULL << lim) - 1ULL);
    }

    g_mask[(o * 8 + ec) * 512 + i] = msk;
}

// ---------------------------------------------------------------------------
// Stage 2: one thread per mask word; exact exp(-L1) for survivors,
// added to BOTH out[i,o] and out[j,o] (j > i). Grid 1024 x 256.
// ---------------------------------------------------------------------------
__global__ __launch_bounds__(256) void stage2_exact(float* __restrict__ out) {
    const int widx = blockIdx.x * 256 + threadIdx.x;   // 0..262143
    ull w = g_mask[widx];
    if (!w) return;

    const int o  = widx >> 12;
    const int ec = (widx >> 9) & 7;
    const int i  = widx & 511;

    const float4* ri = (const float4*)&g_M[i * NN + o * KK];
    float4 a = ri[0], b = ri[1], c = ri[2], d = ri[3];

    float acc = 0.f;
    while (w) {
        int bit = __ffsll((long long)w) - 1;
        w &= w - 1;
        int j = ec * 64 + bit;

        const float4* rj = (const float4*)&g_M[j * NN + o * KK];
        float4 e = rj[0], f = rj[1], g = rj[2], h = rj[3];

        float norm =
            fabsf(a.x - e.x) + fabsf(a.y - e.y) + fabsf(a.z - e.z) + fabsf(a.w - e.w) +
            fabsf(b.x - f.x) + fabsf(b.y - f.y) + fabsf(b.z - f.z) + fabsf(b.w - f.w) +
            fabsf(c.x - g.x) + fabsf(c.y - g.y) + fabsf(c.z - g.z) + fabsf(c.w - g.w) +
            fabsf(d.x - h.x) + fabsf(d.y - h.y) + fabsf(d.z - h.z) + fabsf(d.w - h.w);

        float ev = __expf(-norm);
        if (ev != 0.f) {
            acc += ev;
            atomicAdd(&out[j * OUTCOLS + INF + o], ev);
        }
    }
    if (acc != 0.f)
        atomicAdd(&out[i * OUTCOLS + INF + o], acc);
}

extern "C" void kernel_launch(void* const* d_in, const int* in_sizes, int n_in,
                              void* d_out, int out_size) {
    const float* x = (const float*)d_in[0];
    const float* T = (const float*)d_in[1];
    float* out = (float*)d_out;

    gemm_tc<<<dim3(NN / 64, BB / 16), 256>>>(x, T, out);
    stage1_mask<<<dim3(OUTF + 1, 8), 512>>>(x, out);
    stage2_exact<<<1024, 256>>>(out);
}

// round 10
// speedup vs baseline: 1.3237x; 1.3237x over previous
#include <cuda_runtime.h>

#define BB      512
#define INF     512
#define OUTF    64
#define KK      16
#define NN      1024   // OUTF * KK
#define OUTCOLS 576    // INF + OUTF
#define THRESH  120.0f

typedef unsigned long long ull;

// Scratch (static device allocs are allowed).
__device__ float g_M[BB * NN];              // 2MB: M = x @ T
__device__ float g_G[OUTF * BB * 8];        // 1MB: 8 group-sums per (o,i)
__device__ ull   g_mask[OUTF * 8 * BB];     // 2MB: survivor bitmasks (j>i only)

#define FMA2D(d, a, b, c) \
    asm("fma.rn.f32x2 %0, %1, %2, %3;" : "=l"(d) : "l"(a), "l"(b), "l"(c))
#define ADD2(d, a, b) \
    asm("add.rn.f32x2 %0, %1, %2;" : "=l"(d) : "l"(a), "l"(b))

__device__ __forceinline__ void mma_tf32(float* c, const unsigned* a, const unsigned* b) {
    asm("mma.sync.aligned.m16n8k8.row.col.f32.tf32.tf32.f32 "
        "{%0,%1,%2,%3}, {%4,%5,%6,%7}, {%8,%9}, {%0,%1,%2,%3};"
        : "+f"(c[0]), "+f"(c[1]), "+f"(c[2]), "+f"(c[3])
        : "r"(a[0]), "r"(a[1]), "r"(a[2]), "r"(a[3]), "r"(b[0]), "r"(b[1]));
}

__device__ __forceinline__ void cp16(void* smem_dst, const void* gmem_src) {
    unsigned s = (unsigned)__cvta_generic_to_shared(smem_dst);
    asm volatile("cp.async.cg.shared.global [%0], [%1], 16;" :: "r"(s), "l"(gmem_src));
}

// ---------------------------------------------------------------------------
// GEMM via tf32 tensor cores, 3-stage cp.async pipeline (40.5 KB smem).
// M = x(512x512) @ T(512x1024). Block 128 thr (4 warps, 2x2),
// tile 32x64, warp tile m16 x n32 (3 LDS per MMA), k-tile 32.
// Grid (16,16) = 256 blocks. Epilogue writes g_M + group sums g_G and
// zero-inits out[:,512:576].
// ---------------------------------------------------------------------------
__global__ __launch_bounds__(128) void gemm_tc(const float* __restrict__ x,
                                               const float* __restrict__ T,
                                               float* __restrict__ out) {
    __shared__ float As[3][32][36];   // [stage][row][k], pad 36
    __shared__ float Bs[3][32][72];   // [stage][k][n],  pad 72 (conflict-free gathers)

    const int tid  = threadIdx.x;
    const int warp = tid >> 5;
    const int lane = tid & 31;
    const int wm   = warp & 1;     // m half (0..1)
    const int wn   = warp >> 1;    // n half (0..1)
    const int tg   = lane >> 2;    // 0..7
    const int tig  = lane & 3;     // 0..3

    const int rowBase = blockIdx.y * 32;
    const int colBase = blockIdx.x * 64;

    // Zero-init the o_b region of out (32768 elems = 256 blocks x 128 thr).
    {
        int idx = (blockIdx.y * 16 + blockIdx.x) * 128 + tid;
        out[(idx >> 6) * OUTCOLS + INF + (idx & 63)] = 0.f;
    }

    // cp.async chunk assignment (per k-tile: A 2 chunks/thr, B 4 chunks/thr).
    const int ar0 = tid >> 3;            // A row  (0..15)
    const int ak0 = (tid & 7) * 4;       // A k-quad
    const int br0 = tid >> 4;            // B k row (0..7)
    const int bn0 = (tid & 15) * 4;      // B n-quad

#define ISSUE_TILE(st, k0)                                                        \
    do {                                                                          \
        cp16(&As[st][ar0][ak0],      &x[(rowBase + ar0) * INF + (k0) + ak0]);     \
        cp16(&As[st][ar0 + 16][ak0], &x[(rowBase + ar0 + 16) * INF + (k0) + ak0]);\
        cp16(&Bs[st][br0][bn0],      &T[((k0) + br0) * NN + colBase + bn0]);      \
        cp16(&Bs[st][br0 + 8][bn0],  &T[((k0) + br0 + 8) * NN + colBase + bn0]);  \
        cp16(&Bs[st][br0 + 16][bn0], &T[((k0) + br0 + 16) * NN + colBase + bn0]); \
        cp16(&Bs[st][br0 + 24][bn0], &T[((k0) + br0 + 24) * NN + colBase + bn0]); \
        asm volatile("cp.async.commit_group;");                                   \
    } while (0)

    ISSUE_TILE(0, 0);
    ISSUE_TILE(1, 32);

    float acc[4][4];
#pragma unroll
    for (int nt = 0; nt < 4; ++nt)
#pragma unroll
        for (int q = 0; q < 4; ++q) acc[nt][q] = 0.f;

    // 16 k-tiles, 3 stages: wait so that tile kt is complete (<=1 group in
    // flight), compute, then refill stage (kt+2)%3 == (kt-1)%3 (readers done).
    for (int kt = 0; kt < 16; ++kt) {
        asm volatile("cp.async.wait_group 1;");
        __syncthreads();
        const int st = kt % 3;

#pragma unroll
        for (int ks = 0; ks < 32; ks += 8) {
            unsigned a[4], b[4][2];
            int rowA = wm * 16 + tg;
            a[0] = __float_as_uint(As[st][rowA][ks + tig]);
            a[1] = __float_as_uint(As[st][rowA + 8][ks + tig]);
            a[2] = __float_as_uint(As[st][rowA][ks + tig + 4]);
            a[3] = __float_as_uint(As[st][rowA + 8][ks + tig + 4]);
#pragma unroll
            for (int nt = 0; nt < 4; ++nt) {
                int colB = wn * 32 + nt * 8 + tg;
                b[nt][0] = __float_as_uint(Bs[st][ks + tig][colB]);
                b[nt][1] = __float_as_uint(Bs[st][ks + tig + 4][colB]);
            }
#pragma unroll
            for (int nt = 0; nt < 4; ++nt)
                mma_tf32(acc[nt], a, b[nt]);
        }

        if (kt < 14) {
            // All threads participate (no divergent guard around cp.async).
            const int stn = (kt + 2) % 3;
            const int k0n = (kt + 2) * 32;
            ISSUE_TILE(stn, k0n);
        }
    }
#undef ISSUE_TILE

    // Epilogue: g_M + adjacent-pair group sums g_G.
#pragma unroll
    for (int nt = 0; nt < 4; ++nt) {
        int row0 = rowBase + wm * 16 + tg;
        int col0 = colBase + wn * 32 + nt * 8 + tig * 2;
        int o = col0 >> 4;
        int g = (col0 & 15) >> 1;
        *(float2*)&g_M[row0 * NN + col0]       = make_float2(acc[nt][0], acc[nt][1]);
        *(float2*)&g_M[(row0 + 8) * NN + col0] = make_float2(acc[nt][2], acc[nt][3]);
        g_G[((o << 9) + row0) * 8 + g]     = acc[nt][0] + acc[nt][1];
        g_G[((o << 9) + row0 + 8) * 8 + g] = acc[nt][2] + acc[nt][3];
    }
}

// ---------------------------------------------------------------------------
// Stage 1: symmetric lower-bound filter -> bitmask (bits only for j > i).
// Grid (65, 8), 512 threads. o == 64: copy x rows into out[:, 0:512].
// ---------------------------------------------------------------------------
__global__ __launch_bounds__(512) void stage1_mask(const float* __restrict__ x,
                                                   float* __restrict__ out) {
    __shared__ __align__(16) ull sG[64 * 4];   // 64 j-rows x 4 packed group-pairs

    const int o   = blockIdx.x;
    const int ec  = blockIdx.y;
    const int tid = threadIdx.x;

    if (o == OUTF) {
        int base = ec * 64;
#pragma unroll
        for (int t = tid; t < 64 * (INF / 4); t += 512) {
            int r = t >> 7;
            int c = t & 127;
            float4 v = *(const float4*)&x[(base + r) * INF + c * 4];
            *(float4*)&out[(base + r) * OUTCOLS + c * 4] = v;
        }
        return;
    }

    const int jbase = ec * 64;
    const int i     = tid;
    const int lim   = i - jbase;   // bits jj <= lim cleared (keep j > i)

    if (tid < 128) {
        int r = tid >> 1;
        int h = tid & 1;
        *(float4*)&sG[r * 4 + h * 2] =
            *(const float4*)&g_G[((o << 9) + jbase + r) * 8 + h * 4];
    }

    ull gi[4];
    {
        const ulonglong2* p = (const ulonglong2*)&g_G[((o << 9) + i) * 8];
        ulonglong2 v0 = p[0], v1 = p[1];
        gi[0] = v0.x; gi[1] = v0.y; gi[2] = v1.x; gi[3] = v1.y;
    }
    __syncthreads();

    const ull NEG1  = 0xBF800000BF800000ULL;
    const ull AMASK = 0x7FFFFFFF7FFFFFFFULL;

    ull msk = 0;
    if (lim < 63) {
#pragma unroll
        for (int jj = 0; jj < 64; ++jj) {
            const ulonglong2* p = (const ulonglong2*)&sG[jj * 4];
            ulonglong2 v0 = p[0], v1 = p[1];

            ull d0, d1, d2, d3;
            FMA2D(d0, v0.x, NEG1, gi[0]);
            FMA2D(d1, v0.y, NEG1, gi[1]);
            FMA2D(d2, v1.x, NEG1, gi[2]);
            FMA2D(d3, v1.y, NEG1, gi[3]);
            d0 &= AMASK; d1 &= AMASK; d2 &= AMASK; d3 &= AMASK;

            ull s0, s1, t;
            ADD2(s0, d0, d1);
            ADD2(s1, d2, d3);
            ADD2(t, s0, s1);

            float lb = __uint_as_float((unsigned)t) + __uint_as_float((unsigned)(t >> 32));
            if (lb < THRESH) msk |= (1ULL << jj);
        }
        if (lim >= 0) msk &= ~((2ULL << lim) - 1ULL);
    }

    g_mask[(o * 8 + ec) * 512 + i] = msk;
}

// ---------------------------------------------------------------------------
// Stage 2: one thread per mask word; exact exp(-L1) for survivors,
// added to BOTH out[i,o] and out[j,o] (j > i). Grid 1024 x 256.
// ---------------------------------------------------------------------------
__global__ __launch_bounds__(256) void stage2_exact(float* __restrict__ out) {
    const int widx = blockIdx.x * 256 + threadIdx.x;   // 0..262143
    ull w = g_mask[widx];
    if (!w) return;

    const int o  = widx >> 12;
    const int ec = (widx >> 9) & 7;
    const int i  = widx & 511;

    const float4* ri = (const float4*)&g_M[i * NN + o * KK];
    float4 a = ri[0], b = ri[1], c = ri[2], d = ri[3];

    float acc = 0.f;
    while (w) {
        int bit = __ffsll((long long)w) - 1;
        w &= w - 1;
        int j = ec * 64 + bit;

        const float4* rj = (const float4*)&g_M[j * NN + o * KK];
        float4 e = rj[0], f = rj[1], g = rj[2], h = rj[3];

        float norm =
            fabsf(a.x - e.x) + fabsf(a.y - e.y) + fabsf(a.z - e.z) + fabsf(a.w - e.w) +
            fabsf(b.x - f.x) + fabsf(b.y - f.y) + fabsf(b.z - f.z) + fabsf(b.w - f.w) +
            fabsf(c.x - g.x) + fabsf(c.y - g.y) + fabsf(c.z - g.z) + fabsf(c.w - g.w) +
            fabsf(d.x - h.x) + fabsf(d.y - h.y) + fabsf(d.z - h.z) + fabsf(d.w - h.w);

        float ev = __expf(-norm);
        if (ev != 0.f) {
            acc += ev;
            atomicAdd(&out[j * OUTCOLS + INF + o], ev);
        }
    }
    if (acc != 0.f)
        atomicAdd(&out[i * OUTCOLS + INF + o], acc);
}

extern "C" void kernel_launch(void* const* d_in, const int* in_sizes, int n_in,
                              void* d_out, int out_size) {
    const float* x = (const float*)d_in[0];
    const float* T = (const float*)d_in[1];
    float* out = (float*)d_out;

    gemm_tc<<<dim3(NN / 64, BB / 32), 128>>>(x, T, out);
    stage1_mask<<<dim3(OUTF + 1, 8), 512>>>(x, out);
    stage2_exact<<<1024, 256>>>(out);
}

// round 11
// speedup vs baseline: 1.3251x; 1.0010x over previous
#include <cuda_runtime.h>

#define BB      512
#define INF     512
#define OUTF    64
#define KK      16
#define NN      1024   // OUTF * KK
#define OUTCOLS 576    // INF + OUTF
#define THRESH  120.0f

typedef unsigned long long ull;

// Scratch (static device allocs are allowed).
__device__ float g_M[BB * NN];              // 2MB: M = x @ T
__device__ float g_G[OUTF * BB * 8];        // 1MB: 8 group-sums per (o,i)
__device__ ull   g_mask[OUTF * 8 * BB];     // 2MB: survivor bitmasks (j>i only)

#define FMA2D(d, a, b, c) \
    asm("fma.rn.f32x2 %0, %1, %2, %3;" : "=l"(d) : "l"(a), "l"(b), "l"(c))
#define ADD2(d, a, b) \
    asm("add.rn.f32x2 %0, %1, %2;" : "=l"(d) : "l"(a), "l"(b))

__device__ __forceinline__ void mma_tf32(float* c, const unsigned* a, const unsigned* b) {
    asm("mma.sync.aligned.m16n8k8.row.col.f32.tf32.tf32.f32 "
        "{%0,%1,%2,%3}, {%4,%5,%6,%7}, {%8,%9}, {%0,%1,%2,%3};"
        : "+f"(c[0]), "+f"(c[1]), "+f"(c[2]), "+f"(c[3])
        : "r"(a[0]), "r"(a[1]), "r"(a[2]), "r"(a[3]), "r"(b[0]), "r"(b[1]));
}

__device__ __forceinline__ void cp16(void* smem_dst, const void* gmem_src) {
    unsigned s = (unsigned)__cvta_generic_to_shared(smem_dst);
    asm volatile("cp.async.cg.shared.global [%0], [%1], 16;" :: "r"(s), "l"(gmem_src));
}

// ---------------------------------------------------------------------------
// GEMM via tf32 tensor cores, 3-stage cp.async pipeline + register-level
// fragment double-buffering. M = x(512x512) @ T(512x1024).
// Block 128 thr (4 warps, 2x2), tile 32x64, warp tile m16 x n32, k-tile 32.
// Grid (16,16) = 256 blocks. Epilogue writes g_M + group sums g_G and
// zero-inits out[:,512:576].
// ---------------------------------------------------------------------------
__global__ __launch_bounds__(128) void gemm_tc(const float* __restrict__ x,
                                               const float* __restrict__ T,
                                               float* __restrict__ out) {
    __shared__ float As[3][32][36];   // [stage][row][k], pad 36
    __shared__ float Bs[3][32][72];   // [stage][k][n],  pad 72

    const int tid  = threadIdx.x;
    const int warp = tid >> 5;
    const int lane = tid & 31;
    const int wm   = warp & 1;     // m half
    const int wn   = warp >> 1;    // n half
    const int tg   = lane >> 2;    // 0..7
    const int tig  = lane & 3;     // 0..3

    const int rowBase = blockIdx.y * 32;
    const int colBase = blockIdx.x * 64;

    // Zero-init the o_b region of out (32768 elems = 256 blocks x 128 thr).
    {
        int idx = (blockIdx.y * 16 + blockIdx.x) * 128 + tid;
        out[(idx >> 6) * OUTCOLS + INF + (idx & 63)] = 0.f;
    }

    // cp.async chunk assignment.
    const int ar0 = tid >> 3;            // A row  (0..15)
    const int ak0 = (tid & 7) * 4;       // A k-quad
    const int br0 = tid >> 4;            // B k row (0..7)
    const int bn0 = (tid & 15) * 4;      // B n-quad

#define ISSUE_TILE(st, k0)                                                        \
    do {                                                                          \
        cp16(&As[st][ar0][ak0],      &x[(rowBase + ar0) * INF + (k0) + ak0]);     \
        cp16(&As[st][ar0 + 16][ak0], &x[(rowBase + ar0 + 16) * INF + (k0) + ak0]);\
        cp16(&Bs[st][br0][bn0],      &T[((k0) + br0) * NN + colBase + bn0]);      \
        cp16(&Bs[st][br0 + 8][bn0],  &T[((k0) + br0 + 8) * NN + colBase + bn0]);  \
        cp16(&Bs[st][br0 + 16][bn0], &T[((k0) + br0 + 16) * NN + colBase + bn0]); \
        cp16(&Bs[st][br0 + 24][bn0], &T[((k0) + br0 + 24) * NN + colBase + bn0]); \
        asm volatile("cp.async.commit_group;");                                   \
    } while (0)

// Load one ks-step's fragments (A 4 regs, B 8 regs) from smem stage st.
#define LOADFRAG(aa, bb, st, ks)                                                  \
    do {                                                                          \
        int rowA = wm * 16 + tg;                                                  \
        aa[0] = __float_as_uint(As[st][rowA][(ks) + tig]);                        \
        aa[1] = __float_as_uint(As[st][rowA + 8][(ks) + tig]);                    \
        aa[2] = __float_as_uint(As[st][rowA][(ks) + tig + 4]);                    \
        aa[3] = __float_as_uint(As[st][rowA + 8][(ks) + tig + 4]);                \
        _Pragma("unroll")                                                         \
        for (int nt = 0; nt < 4; ++nt) {                                          \
            int colB = wn * 32 + nt * 8 + tg;                                     \
            bb[nt][0] = __float_as_uint(Bs[st][(ks) + tig][colB]);                \
            bb[nt][1] = __float_as_uint(Bs[st][(ks) + tig + 4][colB]);            \
        }                                                                         \
    } while (0)

    ISSUE_TILE(0, 0);
    ISSUE_TILE(1, 32);

    float acc[4][4];
#pragma unroll
    for (int nt = 0; nt < 4; ++nt)
#pragma unroll
        for (int q = 0; q < 4; ++q) acc[nt][q] = 0.f;

    unsigned afrag[2][4], bfrag[2][4][2];

    for (int kt = 0; kt < 16; ++kt) {
        asm volatile("cp.async.wait_group 1;");
        __syncthreads();
        const int st = kt % 3;

        // Fragment pipeline: prefetch ks+8 while MMAs for ks issue.
        LOADFRAG(afrag[0], bfrag[0], st, 0);
#pragma unroll
        for (int s = 0; s < 4; ++s) {
            const int cur = s & 1;
            const int nxt = cur ^ 1;
            if (s < 3)
                LOADFRAG(afrag[nxt], bfrag[nxt], st, (s + 1) * 8);
#pragma unroll
            for (int nt = 0; nt < 4; ++nt)
                mma_tf32(acc[nt], afrag[cur], bfrag[cur][nt]);
        }

        if (kt < 14) {
            // All threads participate (no divergent guard around cp.async).
            const int stn = (kt + 2) % 3;
            const int k0n = (kt + 2) * 32;
            ISSUE_TILE(stn, k0n);
        }
    }
#undef ISSUE_TILE
#undef LOADFRAG

    // Epilogue: g_M + adjacent-pair group sums g_G.
#pragma unroll
    for (int nt = 0; nt < 4; ++nt) {
        int row0 = rowBase + wm * 16 + tg;
        int col0 = colBase + wn * 32 + nt * 8 + tig * 2;
        int o = col0 >> 4;
        int g = (col0 & 15) >> 1;
        *(float2*)&g_M[row0 * NN + col0]       = make_float2(acc[nt][0], acc[nt][1]);
        *(float2*)&g_M[(row0 + 8) * NN + col0] = make_float2(acc[nt][2], acc[nt][3]);
        g_G[((o << 9) + row0) * 8 + g]     = acc[nt][0] + acc[nt][1];
        g_G[((o << 9) + row0 + 8) * 8 + g] = acc[nt][2] + acc[nt][3];
    }
}

// ---------------------------------------------------------------------------
// Stage 1: symmetric lower-bound filter -> bitmask (bits only for j > i).
// Grid (65, 8), 512 threads. o == 64: copy x rows into out[:, 0:512].
// ---------------------------------------------------------------------------
__global__ __launch_bounds__(512) void stage1_mask(const float* __restrict__ x,
                                                   float* __restrict__ out) {
    __shared__ __align__(16) ull sG[64 * 4];   // 64 j-rows x 4 packed group-pairs

    const int o   = blockIdx.x;
    const int ec  = blockIdx.y;
    const int tid = threadIdx.x;

    if (o == OUTF) {
        int base = ec * 64;
#pragma unroll
        for (int t = tid; t < 64 * (INF / 4); t += 512) {
            int r = t >> 7;
            int c = t & 127;
            float4 v = *(const float4*)&x[(base + r) * INF + c * 4];
            *(float4*)&out[(base + r) * OUTCOLS + c * 4] = v;
        }
        return;
    }

    const int jbase = ec * 64;
    const int i     = tid;
    const int lim   = i - jbase;   // bits jj <= lim cleared (keep j > i)

    if (tid < 128) {
        int r = tid >> 1;
        int h = tid & 1;
        *(float4*)&sG[r * 4 + h * 2] =
            *(const float4*)&g_G[((o << 9) + jbase + r) * 8 + h * 4];
    }

    ull gi[4];
    {
        const ulonglong2* p = (const ulonglong2*)&g_G[((o << 9) + i) * 8];
        ulonglong2 v0 = p[0], v1 = p[1];
        gi[0] = v0.x; gi[1] = v0.y; gi[2] = v1.x; gi[3] = v1.y;
    }
    __syncthreads();

    const ull NEG1  = 0xBF800000BF800000ULL;
    const ull AMASK = 0x7FFFFFFF7FFFFFFFULL;

    ull msk = 0;
    if (lim < 63) {
#pragma unroll
        for (int jj = 0; jj < 64; ++jj) {
            const ulonglong2* p = (const ulonglong2*)&sG[jj * 4];
            ulonglong2 v0 = p[0], v1 = p[1];

            ull d0, d1, d2, d3;
            FMA2D(d0, v0.x, NEG1, gi[0]);
            FMA2D(d1, v0.y, NEG1, gi[1]);
            FMA2D(d2, v1.x, NEG1, gi[2]);
            FMA2D(d3, v1.y, NEG1, gi[3]);
            d0 &= AMASK; d1 &= AMASK; d2 &= AMASK; d3 &= AMASK;

            ull s0, s1, t;
            ADD2(s0, d0, d1);
            ADD2(s1, d2, d3);
            ADD2(t, s0, s1);

            float lb = __uint_as_float((unsigned)t) + __uint_as_float((unsigned)(t >> 32));
            if (lb < THRESH) msk |= (1ULL << jj);
        }
        if (lim >= 0) msk &= ~((2ULL << lim) - 1ULL);
    }

    g_mask[(o * 8 + ec) * 512 + i] = msk;
}

// ---------------------------------------------------------------------------
// Stage 2: one thread per mask word; exact exp(-L1) for survivors,
// added to BOTH out[i,o] and out[j,o] (j > i). Grid 1024 x 256.
// ---------------------------------------------------------------------------
__global__ __launch_bounds__(256) void stage2_exact(float* __restrict__ out) {
    const int widx = blockIdx.x * 256 + threadIdx.x;   // 0..262143
    ull w = g_mask[widx];
    if (!w) return;

    const int o  = widx >> 12;
    const int ec = (widx >> 9) & 7;
    const int i  = widx & 511;

    const float4* ri = (const float4*)&g_M[i * NN + o * KK];
    float4 a = ri[0], b = ri[1], c = ri[2], d = ri[3];

    float acc = 0.f;
    while (w) {
        int bit = __ffsll((long long)w) - 1;
        w &= w - 1;
        int j = ec * 64 + bit;

        const float4* rj = (const float4*)&g_M[j * NN + o * KK];
        float4 e = rj[0], f = rj[1], g = rj[2], h = rj[3];

        float norm =
            fabsf(a.x - e.x) + fabsf(a.y - e.y) + fabsf(a.z - e.z) + fabsf(a.w - e.w) +
            fabsf(b.x - f.x) + fabsf(b.y - f.y) + fabsf(b.z - f.z) + fabsf(b.w - f.w) +
            fabsf(c.x - g.x) + fabsf(c.y - g.y) + fabsf(c.z - g.z) + fabsf(c.w - g.w) +
            fabsf(d.x - h.x) + fabsf(d.y - h.y) + fabsf(d.z - h.z) + fabsf(d.w - h.w);

        float ev = __expf(-norm);
        if (ev != 0.f) {
            acc += ev;
            atomicAdd(&out[j * OUTCOLS + INF + o], ev);
        }
    }
    if (acc != 0.f)
        atomicAdd(&out[i * OUTCOLS + INF + o], acc);
}

extern "C" void kernel_launch(void* const* d_in, const int* in_sizes, int n_in,
                              void* d_out, int out_size) {
    const float* x = (const float*)d_in[0];
    const float* T = (const float*)d_in[1];
    float* out = (float*)d_out;

    gemm_tc<<<dim3(NN / 64, BB / 32), 128>>>(x, T, out);
    stage1_mask<<<dim3(OUTF + 1, 8), 512>>>(x, out);
    stage2_exact<<<1024, 256>>>(out);
}